// round 2
// baseline (speedup 1.0000x reference)
#include <cuda_runtime.h>

// Problem constants
#define EMB   1024
#define NH    16
#define HD    64
#define BATCH 4
#define SEQ   2048
#define MROWS (BATCH*SEQ)          // 8192
#define OUT0_ELEMS (MROWS*EMB)     // 8388608  (output)
#define OUT1_ELEMS (BATCH*NH*SEQ*SEQ) // 268435456 (attn_weights)

// Scratch (allocation-free: __device__ globals)
__device__ float g_q[BATCH*NH*SEQ*HD];
__device__ float g_k[BATCH*NH*SEQ*HD];
__device__ float g_v[BATCH*NH*SEQ*HD];
__device__ float g_att[BATCH*SEQ*EMB];

// ---------------------------------------------------------------------------
// SGEMM: C[M=8192, N=1024] = A[M,1024] @ W[1024,1024] + bias
// 128x128 block tile, BK=8, 256 threads, 8x8 per thread.
// dstmode: 0 -> plain to 'out'; 1/2/3 -> remap into g_q/g_k/g_v as [B,H,S,D]
// srcmode: 0 -> A param; 1 -> g_att
// ---------------------------------------------------------------------------
__global__ __launch_bounds__(256, 2)
void sgemm128(const float* __restrict__ A, const float* __restrict__ W,
              const float* __restrict__ bias, float* __restrict__ out,
              int dstmode, int srcmode)
{
    __shared__ float As[8][128];
    __shared__ float Bs[8][128];

    const float* Ain = srcmode ? (const float*)g_att : A;

    int tid = threadIdx.x;
    int tx = tid & 15, ty = tid >> 4;
    int m0 = blockIdx.y * 128, n0 = blockIdx.x * 128;

    float acc[8][8];
#pragma unroll
    for (int i = 0; i < 8; i++)
#pragma unroll
        for (int j = 0; j < 8; j++) acc[i][j] = 0.f;

    int lam = tid >> 1;            // 0..127 (m within tile)
    int lak = (tid & 1) * 4;       // 0 or 4 (k within tile)
    int lbk = tid >> 5;            // 0..7   (k within tile)
    int lbn = (tid & 31) * 4;      // 0..124 (n within tile)

    const float* Aptr = Ain + (size_t)(m0 + lam) * EMB + lak;
    const float* Wptr = W + (size_t)lbk * EMB + n0 + lbn;

    for (int kb = 0; kb < EMB; kb += 8) {
        float4 a4 = *(const float4*)(Aptr + kb);
        float4 b4 = *(const float4*)(Wptr + (size_t)kb * EMB);
        As[lak+0][lam] = a4.x; As[lak+1][lam] = a4.y;
        As[lak+2][lam] = a4.z; As[lak+3][lam] = a4.w;
        *(float4*)&Bs[lbk][lbn] = b4;
        __syncthreads();
#pragma unroll
        for (int k = 0; k < 8; k++) {
            float ar[8], br[8];
            *(float4*)&ar[0] = *(float4*)&As[k][ty*8];
            *(float4*)&ar[4] = *(float4*)&As[k][ty*8+4];
            *(float4*)&br[0] = *(float4*)&Bs[k][tx*8];
            *(float4*)&br[4] = *(float4*)&Bs[k][tx*8+4];
#pragma unroll
            for (int i = 0; i < 8; i++)
#pragma unroll
                for (int j = 0; j < 8; j++)
                    acc[i][j] += ar[i] * br[j];
        }
        __syncthreads();
    }

    float* dst;
    if      (dstmode == 0) dst = out;
    else if (dstmode == 1) dst = g_q;
    else if (dstmode == 2) dst = g_k;
    else                   dst = g_v;

#pragma unroll
    for (int i = 0; i < 8; i++) {
        int m = m0 + ty*8 + i;
        int b = m >> 11, s = m & 2047;
#pragma unroll
        for (int j4 = 0; j4 < 2; j4++) {
            int n = n0 + tx*8 + j4*4;
            float4 r;
            r.x = acc[i][j4*4+0] + bias[n+0];
            r.y = acc[i][j4*4+1] + bias[n+1];
            r.z = acc[i][j4*4+2] + bias[n+2];
            r.w = acc[i][j4*4+3] + bias[n+3];
            if (dstmode) {
                int h = n >> 6, d = n & 63;
                *(float4*)&dst[(((size_t)(b*NH + h)*SEQ) + s)*HD + d] = r;
            } else {
                *(float4*)&dst[(size_t)m*EMB + n] = r;
            }
        }
    }
}

// ---------------------------------------------------------------------------
// Fused attention: for each (b,h) and 16-row q tile:
//   S = Q Kᵀ / 8   (scores in SMEM, 16x2048)
//   P = softmax(S) (written to attn_weights gmem once, kept in SMEM)
//   O = P V        (accumulated from SMEM, written to merged scratch [B,S,E])
// ---------------------------------------------------------------------------
#define QT 16
#define CK 256
#define NCHUNK (SEQ/CK)
#define PS_STRIDE SEQ      // 2048
#define KS_STRIDE 260      // 64 x 260 (transposed K, padded)
#define VS_STRIDE 68       // 256 x 68 (padded)
#define QS_STRIDE 17
#define KV_FLOATS 17408    // max(64*260, 256*68) = 17408
#define SMEM_FLOATS (QT*PS_STRIDE + KV_FLOATS + 64*QS_STRIDE)
#define SMEM_BYTES  (SMEM_FLOATS * 4)   // 205056 B

__global__ __launch_bounds__(256, 1)
void attn_kernel(float* __restrict__ attnW)
{
    extern __shared__ float sm[];
    float* Ps = sm;                        // [16][2048]
    float* KV = sm + QT*PS_STRIDE;         // K: [64][260] / V: [256][68]
    float* Qs = KV + KV_FLOATS;            // [64][17]

    int tid = threadIdx.x;
    int bh  = blockIdx.y;                  // b*16 + h
    int q0  = blockIdx.x * QT;

    const float* Qb = g_q + (size_t)bh * SEQ * HD;
    const float* Kb = g_k + (size_t)bh * SEQ * HD;
    const float* Vb = g_v + (size_t)bh * SEQ * HD;

    // Load Q tile transposed: Qs[d][qr]
    {
        int qr = tid >> 4;
        int d  = (tid & 15) * 4;
        float4 qv = *(const float4*)(Qb + (size_t)(q0 + qr) * HD + d);
        Qs[(d+0)*QS_STRIDE + qr] = qv.x;
        Qs[(d+1)*QS_STRIDE + qr] = qv.y;
        Qs[(d+2)*QS_STRIDE + qr] = qv.z;
        Qs[(d+3)*QS_STRIDE + qr] = qv.w;
    }

    int qg = tid >> 6;       // 0..3  (4 q-rows each)
    int kg = tid & 63;       // 0..63 (4 keys each)

    // ---- Phase 1: scores ----
    for (int c = 0; c < NCHUNK; c++) {
        __syncthreads();
        // load K chunk transposed: KV[d][key]
        {
            const float4* src = (const float4*)(Kb + (size_t)(c*CK + tid) * HD);
#pragma unroll
            for (int d4 = 0; d4 < 16; d4++) {
                float4 kv = src[d4];
                KV[(d4*4+0)*KS_STRIDE + tid] = kv.x;
                KV[(d4*4+1)*KS_STRIDE + tid] = kv.y;
                KV[(d4*4+2)*KS_STRIDE + tid] = kv.z;
                KV[(d4*4+3)*KS_STRIDE + tid] = kv.w;
            }
        }
        __syncthreads();

        float4 acc[4];
#pragma unroll
        for (int i = 0; i < 4; i++) acc[i] = make_float4(0.f,0.f,0.f,0.f);

#pragma unroll 8
        for (int d = 0; d < 64; d++) {
            float4 kv = *(float4*)&KV[d*KS_STRIDE + kg*4];
#pragma unroll
            for (int i = 0; i < 4; i++) {
                float qv = Qs[d*QS_STRIDE + qg*4 + i];
                acc[i].x += qv*kv.x; acc[i].y += qv*kv.y;
                acc[i].z += qv*kv.z; acc[i].w += qv*kv.w;
            }
        }
        const float scale = 0.125f;  // 1/sqrt(64)
#pragma unroll
        for (int i = 0; i < 4; i++) {
            float4 r = make_float4(acc[i].x*scale, acc[i].y*scale,
                                   acc[i].z*scale, acc[i].w*scale);
            *(float4*)&Ps[(qg*4+i)*PS_STRIDE + c*CK + kg*4] = r;
        }
    }
    __syncthreads();

    // ---- Phase 2: softmax per row + write attn_weights ----
    {
        int row = tid >> 4;   // 0..15
        int ln  = tid & 15;   // 16 threads per row
        float* prow = &Ps[row * PS_STRIDE];

        float mx = -1e30f;
#pragma unroll
        for (int i = 0; i < 32; i++) {
            float4 v = *(float4*)&prow[(i*16 + ln)*4];
            mx = fmaxf(mx, fmaxf(fmaxf(v.x,v.y), fmaxf(v.z,v.w)));
        }
#pragma unroll
        for (int m = 1; m < 16; m <<= 1)
            mx = fmaxf(mx, __shfl_xor_sync(0xffffffffu, mx, m));

        float sum = 0.f;
#pragma unroll
        for (int i = 0; i < 32; i++) {
            float4* p = (float4*)&prow[(i*16 + ln)*4];
            float4 v = *p;
            v.x = __expf(v.x - mx); v.y = __expf(v.y - mx);
            v.z = __expf(v.z - mx); v.w = __expf(v.w - mx);
            sum += v.x + v.y + v.z + v.w;
            *p = v;
        }
#pragma unroll
        for (int m = 1; m < 16; m <<= 1)
            sum += __shfl_xor_sync(0xffffffffu, sum, m);
        float inv = 1.f / sum;

        float* gout = attnW ? attnW + ((size_t)bh*SEQ + (q0+row))*SEQ : (float*)0;
#pragma unroll
        for (int i = 0; i < 32; i++) {
            int kk = (i*16 + ln)*4;
            float4* p = (float4*)&prow[kk];
            float4 v = *p;
            v.x *= inv; v.y *= inv; v.z *= inv; v.w *= inv;
            *p = v;
            if (gout) *(float4*)(gout + kk) = v;
        }
    }

    // ---- Phase 3: O = P @ V ----
    int qr = tid >> 4;
    int dg = tid & 15;
    float4 o = make_float4(0.f,0.f,0.f,0.f);
    for (int c = 0; c < NCHUNK; c++) {
        __syncthreads();
        {
            int d4 = (tid & 15) * 4;
            int kb = tid >> 4;
#pragma unroll
            for (int i = 0; i < 16; i++) {
                int key = kb + i*16;
                float4 v = *(const float4*)(Vb + (size_t)(c*CK + key)*HD + d4);
                *(float4*)&KV[key*VS_STRIDE + d4] = v;
            }
        }
        __syncthreads();
        const float* prow = &Ps[qr*PS_STRIDE + c*CK];
#pragma unroll 8
        for (int k = 0; k < CK; k++) {
            float p = prow[k];
            float4 v = *(float4*)&KV[k*VS_STRIDE + dg*4];
            o.x += p*v.x; o.y += p*v.y; o.z += p*v.z; o.w += p*v.w;
        }
    }
    int b = bh >> 4, h = bh & 15;
    *(float4*)&g_att[((size_t)(b*SEQ + q0 + qr))*EMB + h*HD + dg*4] = o;
}

// ---------------------------------------------------------------------------
extern "C" void kernel_launch(void* const* d_in, const int* in_sizes, int n_in,
                              void* d_out, int out_size)
{
    const float* x  = (const float*)d_in[0];
    const float* wq = (const float*)d_in[1];
    const float* wk = (const float*)d_in[2];
    const float* wv = (const float*)d_in[3];
    const float* wo = (const float*)d_in[4];
    const float* bq = (const float*)d_in[5];
    const float* bk = (const float*)d_in[6];
    const float* bv = (const float*)d_in[7];
    const float* bo = (const float*)d_in[8];
    float* out = (float*)d_out;

    // attn_weights goes right after output if the harness expects both.
    float* attnW = (out_size >= (OUT0_ELEMS + OUT1_ELEMS)) ? (out + OUT0_ELEMS)
                                                           : (float*)0;

    cudaFuncSetAttribute(attn_kernel,
                         cudaFuncAttributeMaxDynamicSharedMemorySize, SMEM_BYTES);

    dim3 gg(EMB/128, MROWS/128);   // (8, 64)
    sgemm128<<<gg, 256>>>(x, wq, bq, (float*)0, 1, 0);
    sgemm128<<<gg, 256>>>(x, wk, bk, (float*)0, 2, 0);
    sgemm128<<<gg, 256>>>(x, wv, bv, (float*)0, 3, 0);

    attn_kernel<<<dim3(SEQ/QT, BATCH*NH), 256, SMEM_BYTES>>>(attnW);

    sgemm128<<<gg, 256>>>((const float*)0, wo, bo, out, 0, 1);
}

// round 4
// speedup vs baseline: 1.0790x; 1.0790x over previous
#include <cuda_runtime.h>
#include <cuda_bf16.h>
#include <stdint.h>

// ---------------------------------------------------------------------------
// Problem constants
// ---------------------------------------------------------------------------
#define EMB   1024
#define NH    16
#define HD    64
#define BATCH 4
#define SEQ   2048
#define MROWS (BATCH*SEQ)              // 8192
#define OUT0_ELEMS (MROWS*EMB)         // 8388608  (output)
#define OUT1_ELEMS (BATCH*NH*SEQ*SEQ)  // 268435456 (attn_weights)

// Scratch (allocation-free: __device__ globals)
__device__ float g_q[BATCH*NH*SEQ*HD];
__device__ float g_k[BATCH*NH*SEQ*HD];
__device__ float g_v[BATCH*NH*SEQ*HD];
__device__ float g_att[BATCH*SEQ*EMB];
__device__ __nv_bfloat16 g_xhi[MROWS*EMB];
__device__ __nv_bfloat16 g_xlo[MROWS*EMB];
__device__ __nv_bfloat16 g_wthi[4*EMB*EMB];   // transposed weights [w][n][k]
__device__ __nv_bfloat16 g_wtlo[4*EMB*EMB];

// ---------------------------------------------------------------------------
// helpers
// ---------------------------------------------------------------------------
__device__ __forceinline__ uint32_t smem_u32(const void* p) {
    uint32_t a;
    asm("{ .reg .u64 t; cvta.to.shared.u64 t, %1; cvt.u32.u64 %0, t; }"
        : "=r"(a) : "l"(p));
    return a;
}
__device__ __forceinline__ void ldm_x4(uint32_t* r, uint32_t addr) {
    asm volatile("ldmatrix.sync.aligned.m8n8.x4.shared.b16 {%0,%1,%2,%3}, [%4];"
        : "=r"(r[0]), "=r"(r[1]), "=r"(r[2]), "=r"(r[3]) : "r"(addr));
}
__device__ __forceinline__ void mma_bf16(float* c, const uint32_t* a, const uint32_t* b) {
    asm volatile("mma.sync.aligned.m16n8k16.row.col.f32.bf16.bf16.f32 "
        "{%0,%1,%2,%3}, {%4,%5,%6,%7}, {%8,%9}, {%0,%1,%2,%3};"
        : "+f"(c[0]), "+f"(c[1]), "+f"(c[2]), "+f"(c[3])
        : "r"(a[0]), "r"(a[1]), "r"(a[2]), "r"(a[3]), "r"(b[0]), "r"(b[1]));
}
__device__ __forceinline__ void cp16(uint32_t saddr, const void* gaddr) {
    asm volatile("cp.async.cg.shared.global [%0], [%1], 16;" :: "r"(saddr), "l"(gaddr));
}

// ---------------------------------------------------------------------------
// split kernels: fp32 -> bf16 hi/lo
// ---------------------------------------------------------------------------
__global__ void split_w(const float* __restrict__ wq, const float* __restrict__ wk,
                        const float* __restrict__ wv, const float* __restrict__ wo)
{
    __shared__ float t[32][33];
    int z = blockIdx.z;
    const float* W = (z == 0) ? wq : (z == 1) ? wk : (z == 2) ? wv : wo;
    int n0 = blockIdx.x * 32, k0 = blockIdx.y * 32;
    int tx = threadIdx.x, ty = threadIdx.y;
    t[ty][tx] = W[(size_t)(k0 + ty) * EMB + n0 + tx];
    __syncthreads();
    float v = t[tx][ty];                        // = W[k0+tx][n0+ty]
    __nv_bfloat16 hi = __float2bfloat16(v);
    __nv_bfloat16 lo = __float2bfloat16(v - __bfloat162float(hi));
    size_t o = (size_t)z * (EMB*EMB) + (size_t)(n0 + ty) * EMB + (k0 + tx);
    g_wthi[o] = hi;
    g_wtlo[o] = lo;
}

__global__ void split_x(const float* __restrict__ src, int from_gatt)
{
    int i = (blockIdx.x * 256 + threadIdx.x) * 4;
    float4 v = from_gatt ? *(const float4*)&g_att[i] : *(const float4*)&src[i];
    __nv_bfloat16 h0 = __float2bfloat16(v.x);
    __nv_bfloat16 h1 = __float2bfloat16(v.y);
    __nv_bfloat16 h2 = __float2bfloat16(v.z);
    __nv_bfloat16 h3 = __float2bfloat16(v.w);
    __nv_bfloat162 hA; hA.x = h0; hA.y = h1;
    __nv_bfloat162 hB; hB.x = h2; hB.y = h3;
    *(__nv_bfloat162*)&g_xhi[i]   = hA;
    *(__nv_bfloat162*)&g_xhi[i+2] = hB;
    __nv_bfloat162 lA, lB;
    lA.x = __float2bfloat16(v.x - __bfloat162float(h0));
    lA.y = __float2bfloat16(v.y - __bfloat162float(h1));
    lB.x = __float2bfloat16(v.z - __bfloat162float(h2));
    lB.y = __float2bfloat16(v.w - __bfloat162float(h3));
    *(__nv_bfloat162*)&g_xlo[i]   = lA;
    *(__nv_bfloat162*)&g_xlo[i+2] = lB;
}

// ---------------------------------------------------------------------------
// HMMA 3xbf16 GEMM: C[8192,1024] = (xhi+xlo) @ (Wt hi+lo)^T + bias
// CTA tile 128x128, KC=32 (2 k-steps of 16), cp.async double buffered.
// 8 warps = 2(m) x 4(n), each warp 64x32 via 4x4 m16n8 tiles, 3 products.
// dstmode: 0 -> out [M][E]; 1/2/3 -> g_q/g_k/g_v as [B,H,S,D]
// ---------------------------------------------------------------------------
#define KC       32
#define NCH      (EMB/KC)          // 32
#define TSTRIDE  40                // bf16 elems per smem row (80B, conflict-free)
#define TILE_B   (128*TSTRIDE*2)   // 10240 bytes
#define BUF_B    (4*TILE_B)        // Ahi, Alo, Bhi, Blo
#define GSMEM    (2*BUF_B)         // 81920

__global__ __launch_bounds__(256)
void gemm_hmma(const float* __restrict__ bias, float* __restrict__ out,
               int widx, int dstmode)
{
    extern __shared__ char smc[];
    uint32_t smb = smem_u32(smc);
    int tid = threadIdx.x, wid = tid >> 5, lane = tid & 31;
    int m0 = blockIdx.y * 128, n0 = blockIdx.x * 128;
    int wm = (wid >> 2) * 64, wn = (wid & 3) * 32;

    const __nv_bfloat16* srcs[4];
    srcs[0] = g_xhi + (size_t)m0 * EMB;
    srcs[1] = g_xlo + (size_t)m0 * EMB;
    srcs[2] = g_wthi + (size_t)widx * (EMB*EMB) + (size_t)n0 * EMB;
    srcs[3] = g_wtlo + (size_t)widx * (EMB*EMB) + (size_t)n0 * EMB;

    float acc[4][4][4];
#pragma unroll
    for (int a = 0; a < 4; a++)
#pragma unroll
        for (int b = 0; b < 4; b++)
#pragma unroll
            for (int c = 0; c < 4; c++) acc[a][b][c] = 0.f;

    // --- prefetch chunk 0 ---
    {
        int buf = 0, kc = 0;
#pragma unroll
        for (int t = 0; t < 4; t++)
#pragma unroll
            for (int h = 0; h < 2; h++) {
                int s = tid + h * 256;
                int row = s >> 2, c8 = (s & 3) * 8;
                cp16(smb + buf*BUF_B + t*TILE_B + (row*TSTRIDE + c8)*2,
                     srcs[t] + (size_t)row * EMB + kc*KC + c8);
            }
        asm volatile("cp.async.commit_group;");
    }

    for (int kc = 0; kc < NCH; kc++) {
        int buf = kc & 1;
        if (kc + 1 < NCH) {
            int nb = (kc + 1) & 1;
#pragma unroll
            for (int t = 0; t < 4; t++)
#pragma unroll
                for (int h = 0; h < 2; h++) {
                    int s = tid + h * 256;
                    int row = s >> 2, c8 = (s & 3) * 8;
                    cp16(smb + nb*BUF_B + t*TILE_B + (row*TSTRIDE + c8)*2,
                         srcs[t] + (size_t)row * EMB + (kc+1)*KC + c8);
                }
            asm volatile("cp.async.commit_group;");
            asm volatile("cp.async.wait_group 1;");
        } else {
            asm volatile("cp.async.wait_group 0;");
        }
        __syncthreads();

        uint32_t base = smb + buf * BUF_B;
        int r = lane & 7, sel = lane >> 3;
#pragma unroll
        for (int ks = 0; ks < 2; ks++) {
            int k0 = ks * 16;
            int arow = wm + ((sel & 1) ? 8 : 0) + r;
            int acol = k0 + ((sel & 2) ? 8 : 0);
            uint32_t ah[4][4], al[4][4];
#pragma unroll
            for (int mi = 0; mi < 4; mi++) {
                uint32_t ad = base + (( (arow + mi*16) * TSTRIDE + acol) * 2);
                ldm_x4(ah[mi], ad);
                ldm_x4(al[mi], ad + TILE_B);
            }
            int brow = wn + ((sel & 2) ? 8 : 0) + r;
            int bcol = k0 + ((sel & 1) ? 8 : 0);
            uint32_t bh[4][2], bl[4][2];
#pragma unroll
            for (int p = 0; p < 2; p++) {
                uint32_t t4[4];
                uint32_t bd = base + 2*TILE_B + (((brow + p*16) * TSTRIDE + bcol) * 2);
                ldm_x4(t4, bd);
                bh[p*2][0] = t4[0]; bh[p*2][1] = t4[1];
                bh[p*2+1][0] = t4[2]; bh[p*2+1][1] = t4[3];
                ldm_x4(t4, bd + TILE_B);
                bl[p*2][0] = t4[0]; bl[p*2][1] = t4[1];
                bl[p*2+1][0] = t4[2]; bl[p*2+1][1] = t4[3];
            }
#pragma unroll
            for (int mi = 0; mi < 4; mi++)
#pragma unroll
                for (int ni = 0; ni < 4; ni++) {
                    mma_bf16(acc[mi][ni], ah[mi], bh[ni]);
                    mma_bf16(acc[mi][ni], ah[mi], bl[ni]);
                    mma_bf16(acc[mi][ni], al[mi], bh[ni]);
                }
        }
        __syncthreads();
    }

    // --- epilogue ---
    int rq = lane >> 2, cq = (lane & 3) * 2;
#pragma unroll
    for (int mi = 0; mi < 4; mi++)
#pragma unroll
        for (int hh = 0; hh < 2; hh++) {
            int m = m0 + wm + mi*16 + rq + hh*8;
            int b = m >> 11, s = m & 2047;
#pragma unroll
            for (int ni = 0; ni < 4; ni++) {
                int n = n0 + wn + ni*8 + cq;
                float2 v;
                v.x = acc[mi][ni][hh*2+0] + bias[n];
                v.y = acc[mi][ni][hh*2+1] + bias[n+1];
                if (dstmode) {
                    float* dst = (dstmode == 1) ? g_q : (dstmode == 2) ? g_k : g_v;
                    int h = n >> 6, d = n & 63;
                    *(float2*)&dst[(((size_t)(b*NH + h)*SEQ) + s)*HD + d] = v;
                } else {
                    *(float2*)&out[(size_t)m*EMB + n] = v;
                }
            }
        }
}

// ---------------------------------------------------------------------------
// Fused attention, 512 threads: per (b,h) and 16-row q tile:
//   S = Q K^T / 8 ; P = softmax(S) -> attnW ; O = P V -> g_att
// ---------------------------------------------------------------------------
#define QT 16
#define CK 256
#define NCHUNK (SEQ/CK)
#define PS_STRIDE SEQ
#define KS_STRIDE 260
#define VS_STRIDE 68
#define QS_STRIDE 17
#define KV_FLOATS 17408
#define SMEM_FLOATS (QT*PS_STRIDE + KV_FLOATS + 64*QS_STRIDE)
#define SMEM_BYTES  (SMEM_FLOATS * 4)
#define NT 512

__global__ __launch_bounds__(NT, 1)
void attn_kernel(float* __restrict__ attnW)
{
    extern __shared__ float sm[];
    float* Ps = sm;                        // [16][2048]
    float* KV = sm + QT*PS_STRIDE;         // K: [64][260] / V: [256][68]
    float* Qs = KV + KV_FLOATS;            // [64][17]

    int tid = threadIdx.x;
    int bh  = blockIdx.y;
    int q0  = blockIdx.x * QT;

    const float* Qb = g_q + (size_t)bh * SEQ * HD;
    const float* Kb = g_k + (size_t)bh * SEQ * HD;
    const float* Vb = g_v + (size_t)bh * SEQ * HD;

    // Load Q tile transposed: Qs[d][qr]
    if (tid < 256) {
        int qr = tid >> 4;
        int d  = (tid & 15) * 4;
        float4 qv = *(const float4*)(Qb + (size_t)(q0 + qr) * HD + d);
        Qs[(d+0)*QS_STRIDE + qr] = qv.x;
        Qs[(d+1)*QS_STRIDE + qr] = qv.y;
        Qs[(d+2)*QS_STRIDE + qr] = qv.z;
        Qs[(d+3)*QS_STRIDE + qr] = qv.w;
    }

    int qg = tid >> 7;       // 0..3  (4 q-rows each)
    int kg = tid & 127;      // 0..127 (2 keys each)

    // ---- Phase 1: scores ----
    for (int c = 0; c < NCHUNK; c++) {
        __syncthreads();
        // load K chunk transposed: KV[d][key]  (2 threads per key)
        {
            int key = tid >> 1;
            int db  = (tid & 1) * 8;
            const float4* src = (const float4*)(Kb + (size_t)(c*CK + key) * HD);
#pragma unroll
            for (int j = 0; j < 8; j++) {
                int d4 = db + j;
                float4 kv = src[d4];
                KV[(d4*4+0)*KS_STRIDE + key] = kv.x;
                KV[(d4*4+1)*KS_STRIDE + key] = kv.y;
                KV[(d4*4+2)*KS_STRIDE + key] = kv.z;
                KV[(d4*4+3)*KS_STRIDE + key] = kv.w;
            }
        }
        __syncthreads();

        float2 acc[4];
#pragma unroll
        for (int i = 0; i < 4; i++) acc[i] = make_float2(0.f, 0.f);

#pragma unroll 8
        for (int d = 0; d < 64; d++) {
            float2 kv = *(float2*)&KV[d*KS_STRIDE + kg*2];
#pragma unroll
            for (int i = 0; i < 4; i++) {
                float qv = Qs[d*QS_STRIDE + qg*4 + i];
                acc[i].x += qv*kv.x; acc[i].y += qv*kv.y;
            }
        }
        const float scale = 0.125f;  // 1/sqrt(64)
#pragma unroll
        for (int i = 0; i < 4; i++) {
            float2 r = make_float2(acc[i].x*scale, acc[i].y*scale);
            *(float2*)&Ps[(qg*4+i)*PS_STRIDE + c*CK + kg*2] = r;
        }
    }
    __syncthreads();

    // ---- Phase 2: softmax (one warp per row) + write attn_weights ----
    {
        int row = tid >> 5;   // 0..15
        int ln  = tid & 31;
        float* prow = &Ps[row * PS_STRIDE];

        float mx = -1e30f;
#pragma unroll
        for (int i = 0; i < 16; i++) {
            float4 v = *(float4*)&prow[(i*32 + ln)*4];
            mx = fmaxf(mx, fmaxf(fmaxf(v.x,v.y), fmaxf(v.z,v.w)));
        }
#pragma unroll
        for (int m = 1; m < 32; m <<= 1)
            mx = fmaxf(mx, __shfl_xor_sync(0xffffffffu, mx, m));

        float sum = 0.f;
#pragma unroll
        for (int i = 0; i < 16; i++) {
            float4* p = (float4*)&prow[(i*32 + ln)*4];
            float4 v = *p;
            v.x = __expf(v.x - mx); v.y = __expf(v.y - mx);
            v.z = __expf(v.z - mx); v.w = __expf(v.w - mx);
            sum += v.x + v.y + v.z + v.w;
            *p = v;
        }
#pragma unroll
        for (int m = 1; m < 32; m <<= 1)
            sum += __shfl_xor_sync(0xffffffffu, sum, m);
        float inv = 1.f / sum;

        float* gout = attnW ? attnW + ((size_t)bh*SEQ + (q0+row))*SEQ : (float*)0;
#pragma unroll
        for (int i = 0; i < 16; i++) {
            int kk = (i*32 + ln)*4;
            float4* p = (float4*)&prow[kk];
            float4 v = *p;
            v.x *= inv; v.y *= inv; v.z *= inv; v.w *= inv;
            *p = v;
            if (gout) *(float4*)(gout + kk) = v;
        }
    }

    // ---- Phase 3: O = P @ V (one warp per row, 2 dims per lane) ----
    int qr = tid >> 5;
    int ln = tid & 31;
    float2 o = make_float2(0.f, 0.f);
    for (int c = 0; c < NCHUNK; c++) {
        __syncthreads();
        {
            int d4 = (tid & 15) * 4;
            int kb = tid >> 4;    // 0..31
#pragma unroll
            for (int i = 0; i < 8; i++) {
                int key = kb + i*32;
                float4 v = *(const float4*)(Vb + (size_t)(c*CK + key)*HD + d4);
                *(float4*)&KV[key*VS_STRIDE + d4] = v;
            }
        }
        __syncthreads();
        const float* prow = &Ps[qr*PS_STRIDE + c*CK];
#pragma unroll 8
        for (int k = 0; k < CK; k++) {
            float p = prow[k];
            float2 v = *(float2*)&KV[k*VS_STRIDE + ln*2];
            o.x += p*v.x; o.y += p*v.y;
        }
    }
    int b = bh >> 4, h = bh & 15;
    *(float2*)&g_att[((size_t)(b*SEQ + q0 + qr))*EMB + h*HD + ln*2] = o;
}

// ---------------------------------------------------------------------------
extern "C" void kernel_launch(void* const* d_in, const int* in_sizes, int n_in,
                              void* d_out, int out_size)
{
    const float* x  = (const float*)d_in[0];
    const float* bq = (const float*)d_in[5];
    const float* bk = (const float*)d_in[6];
    const float* bv = (const float*)d_in[7];
    const float* bo = (const float*)d_in[8];
    float* out = (float*)d_out;

    float* attnW = (out_size >= (OUT0_ELEMS + OUT1_ELEMS)) ? (out + OUT0_ELEMS)
                                                           : (float*)0;

    cudaFuncSetAttribute(attn_kernel,
                         cudaFuncAttributeMaxDynamicSharedMemorySize, SMEM_BYTES);
    cudaFuncSetAttribute(gemm_hmma,
                         cudaFuncAttributeMaxDynamicSharedMemorySize, GSMEM);

    // Split weights (transposed) and x into bf16 hi/lo
    split_w<<<dim3(32, 32, 4), dim3(32, 32)>>>(
        (const float*)d_in[1], (const float*)d_in[2],
        (const float*)d_in[3], (const float*)d_in[4]);
    split_x<<<MROWS*EMB/(256*4), 256>>>(x, 0);

    dim3 gg(EMB/128, MROWS/128);   // (8, 64)
    gemm_hmma<<<gg, 256, GSMEM>>>(bq, (float*)0, 0, 1);
    gemm_hmma<<<gg, 256, GSMEM>>>(bk, (float*)0, 1, 2);
    gemm_hmma<<<gg, 256, GSMEM>>>(bv, (float*)0, 2, 3);

    attn_kernel<<<dim3(SEQ/QT, BATCH*NH), NT, SMEM_BYTES>>>(attnW);

    split_x<<<MROWS*EMB/(256*4), 256>>>((const float*)0, 1);
    gemm_hmma<<<gg, 256, GSMEM>>>(bo, out, 3, 0);
}

// round 5
// speedup vs baseline: 3.6381x; 3.3716x over previous
#include <cuda_runtime.h>
#include <cuda_bf16.h>
#include <stdint.h>

// ---------------------------------------------------------------------------
// Problem constants
// ---------------------------------------------------------------------------
#define EMB   1024
#define NH    16
#define HD    64
#define BATCH 4
#define SEQ   2048
#define MROWS (BATCH*SEQ)              // 8192
#define OUT0_ELEMS (MROWS*EMB)         // 8388608  (output)
#define OUT1_ELEMS (BATCH*NH*SEQ*SEQ)  // 268435456 (attn_weights)

// Scratch (allocation-free: __device__ globals)
__device__ __nv_bfloat16 g_xhi[MROWS*EMB];
__device__ __nv_bfloat16 g_xlo[MROWS*EMB];
__device__ __nv_bfloat16 g_wthi[4*EMB*EMB];   // transposed weights [w][n][k]
__device__ __nv_bfloat16 g_wtlo[4*EMB*EMB];
__device__ __nv_bfloat16 g_qhi[BATCH*NH*SEQ*HD];
__device__ __nv_bfloat16 g_qlo[BATCH*NH*SEQ*HD];
__device__ __nv_bfloat16 g_khi[BATCH*NH*SEQ*HD];
__device__ __nv_bfloat16 g_klo[BATCH*NH*SEQ*HD];
__device__ __nv_bfloat16 g_vhi[BATCH*NH*SEQ*HD];
__device__ __nv_bfloat16 g_vlo[BATCH*NH*SEQ*HD];
__device__ float g_s_fallback[OUT1_ELEMS];    // used only if attnW not in d_out

// ---------------------------------------------------------------------------
// helpers
// ---------------------------------------------------------------------------
__device__ __forceinline__ uint32_t smem_u32(const void* p) {
    uint32_t a;
    asm("{ .reg .u64 t; cvta.to.shared.u64 t, %1; cvt.u32.u64 %0, t; }"
        : "=r"(a) : "l"(p));
    return a;
}
__device__ __forceinline__ void ldm_x4(uint32_t* r, uint32_t addr) {
    asm volatile("ldmatrix.sync.aligned.m8n8.x4.shared.b16 {%0,%1,%2,%3}, [%4];"
        : "=r"(r[0]), "=r"(r[1]), "=r"(r[2]), "=r"(r[3]) : "r"(addr));
}
__device__ __forceinline__ void ldm_x4_t(uint32_t* r, uint32_t addr) {
    asm volatile("ldmatrix.sync.aligned.m8n8.x4.trans.shared.b16 {%0,%1,%2,%3}, [%4];"
        : "=r"(r[0]), "=r"(r[1]), "=r"(r[2]), "=r"(r[3]) : "r"(addr));
}
__device__ __forceinline__ void mma_bf16(float* c, const uint32_t* a, const uint32_t* b) {
    asm volatile("mma.sync.aligned.m16n8k16.row.col.f32.bf16.bf16.f32 "
        "{%0,%1,%2,%3}, {%4,%5,%6,%7}, {%8,%9}, {%0,%1,%2,%3};"
        : "+f"(c[0]), "+f"(c[1]), "+f"(c[2]), "+f"(c[3])
        : "r"(a[0]), "r"(a[1]), "r"(a[2]), "r"(a[3]), "r"(b[0]), "r"(b[1]));
}
__device__ __forceinline__ void cp16(uint32_t saddr, const void* gaddr) {
    asm volatile("cp.async.cg.shared.global [%0], [%1], 16;" :: "r"(saddr), "l"(gaddr));
}
__device__ __forceinline__ __nv_bfloat162 hi2_of(float x, float y) {
    __nv_bfloat162 h; h.x = __float2bfloat16(x); h.y = __float2bfloat16(y);
    return h;
}
__device__ __forceinline__ __nv_bfloat162 lo2_of(float x, float y, __nv_bfloat162 h) {
    __nv_bfloat162 l;
    l.x = __float2bfloat16(x - __bfloat162float(h.x));
    l.y = __float2bfloat16(y - __bfloat162float(h.y));
    return l;
}

// ---------------------------------------------------------------------------
// split kernels: fp32 -> bf16 hi/lo
// ---------------------------------------------------------------------------
__global__ void split_w(const float* __restrict__ wq, const float* __restrict__ wk,
                        const float* __restrict__ wv, const float* __restrict__ wo)
{
    __shared__ float t[32][33];
    int z = blockIdx.z;
    const float* W = (z == 0) ? wq : (z == 1) ? wk : (z == 2) ? wv : wo;
    int n0 = blockIdx.x * 32, k0 = blockIdx.y * 32;
    int tx = threadIdx.x, ty = threadIdx.y;
    t[ty][tx] = W[(size_t)(k0 + ty) * EMB + n0 + tx];
    __syncthreads();
    float v = t[tx][ty];                        // = W[k0+tx][n0+ty]
    __nv_bfloat16 hi = __float2bfloat16(v);
    __nv_bfloat16 lo = __float2bfloat16(v - __bfloat162float(hi));
    size_t o = (size_t)z * (EMB*EMB) + (size_t)(n0 + ty) * EMB + (k0 + tx);
    g_wthi[o] = hi;
    g_wtlo[o] = lo;
}

__global__ void split_x(const float* __restrict__ src)
{
    int i = (blockIdx.x * 256 + threadIdx.x) * 4;
    float4 v = *(const float4*)&src[i];
    __nv_bfloat162 hA = hi2_of(v.x, v.y);
    __nv_bfloat162 hB = hi2_of(v.z, v.w);
    *(__nv_bfloat162*)&g_xhi[i]   = hA;
    *(__nv_bfloat162*)&g_xhi[i+2] = hB;
    *(__nv_bfloat162*)&g_xlo[i]   = lo2_of(v.x, v.y, hA);
    *(__nv_bfloat162*)&g_xlo[i+2] = lo2_of(v.z, v.w, hB);
}

// ---------------------------------------------------------------------------
// HMMA 3xbf16 GEMM: C[8192,1024] = (xhi+xlo) @ (Wt hi+lo)^T + bias
// dstmode 0: fp32 -> out [M][E]
// dstmode 1/2/3: bf16 hi/lo -> g_q/g_k/g_v (Q scaled by 1/8, exact)
// ---------------------------------------------------------------------------
#define KC       32
#define NCH      (EMB/KC)          // 32
#define TSTRIDE  40                // bf16 elems per smem row (80B, conflict-free)
#define TILE_B   (128*TSTRIDE*2)   // 10240 bytes
#define BUF_B    (4*TILE_B)        // Ahi, Alo, Bhi, Blo
#define GSMEM    (2*BUF_B)         // 81920

__global__ __launch_bounds__(256)
void gemm_hmma(const float* __restrict__ bias, float* __restrict__ out,
               int widx, int dstmode)
{
    extern __shared__ char smc[];
    uint32_t smb = smem_u32(smc);
    int tid = threadIdx.x, wid = tid >> 5, lane = tid & 31;
    int m0 = blockIdx.y * 128, n0 = blockIdx.x * 128;
    int wm = (wid >> 2) * 64, wn = (wid & 3) * 32;

    const __nv_bfloat16* srcs[4];
    srcs[0] = g_xhi + (size_t)m0 * EMB;
    srcs[1] = g_xlo + (size_t)m0 * EMB;
    srcs[2] = g_wthi + (size_t)widx * (EMB*EMB) + (size_t)n0 * EMB;
    srcs[3] = g_wtlo + (size_t)widx * (EMB*EMB) + (size_t)n0 * EMB;

    float acc[4][4][4];
#pragma unroll
    for (int a = 0; a < 4; a++)
#pragma unroll
        for (int b = 0; b < 4; b++)
#pragma unroll
            for (int c = 0; c < 4; c++) acc[a][b][c] = 0.f;

    // --- prefetch chunk 0 ---
    {
#pragma unroll
        for (int t = 0; t < 4; t++)
#pragma unroll
            for (int h = 0; h < 2; h++) {
                int s = tid + h * 256;
                int row = s >> 2, c8 = (s & 3) * 8;
                cp16(smb + t*TILE_B + (row*TSTRIDE + c8)*2,
                     srcs[t] + (size_t)row * EMB + c8);
            }
        asm volatile("cp.async.commit_group;");
    }

    for (int kc = 0; kc < NCH; kc++) {
        int buf = kc & 1;
        if (kc + 1 < NCH) {
            int nb = (kc + 1) & 1;
#pragma unroll
            for (int t = 0; t < 4; t++)
#pragma unroll
                for (int h = 0; h < 2; h++) {
                    int s = tid + h * 256;
                    int row = s >> 2, c8 = (s & 3) * 8;
                    cp16(smb + nb*BUF_B + t*TILE_B + (row*TSTRIDE + c8)*2,
                         srcs[t] + (size_t)row * EMB + (kc+1)*KC + c8);
                }
            asm volatile("cp.async.commit_group;");
            asm volatile("cp.async.wait_group 1;");
        } else {
            asm volatile("cp.async.wait_group 0;");
        }
        __syncthreads();

        uint32_t base = smb + buf * BUF_B;
        int r = lane & 7, sel = lane >> 3;
#pragma unroll
        for (int ks = 0; ks < 2; ks++) {
            int k0 = ks * 16;
            int arow = wm + ((sel & 1) ? 8 : 0) + r;
            int acol = k0 + ((sel & 2) ? 8 : 0);
            uint32_t ah[4][4], al[4][4];
#pragma unroll
            for (int mi = 0; mi < 4; mi++) {
                uint32_t ad = base + (((arow + mi*16) * TSTRIDE + acol) * 2);
                ldm_x4(ah[mi], ad);
                ldm_x4(al[mi], ad + TILE_B);
            }
            int brow = wn + ((sel & 2) ? 8 : 0) + r;
            int bcol = k0 + ((sel & 1) ? 8 : 0);
            uint32_t bh[4][2], bl[4][2];
#pragma unroll
            for (int p = 0; p < 2; p++) {
                uint32_t t4[4];
                uint32_t bd = base + 2*TILE_B + (((brow + p*16) * TSTRIDE + bcol) * 2);
                ldm_x4(t4, bd);
                bh[p*2][0] = t4[0]; bh[p*2][1] = t4[1];
                bh[p*2+1][0] = t4[2]; bh[p*2+1][1] = t4[3];
                ldm_x4(t4, bd + TILE_B);
                bl[p*2][0] = t4[0]; bl[p*2][1] = t4[1];
                bl[p*2+1][0] = t4[2]; bl[p*2+1][1] = t4[3];
            }
#pragma unroll
            for (int mi = 0; mi < 4; mi++)
#pragma unroll
                for (int ni = 0; ni < 4; ni++) {
                    mma_bf16(acc[mi][ni], ah[mi], bh[ni]);
                    mma_bf16(acc[mi][ni], ah[mi], bl[ni]);
                    mma_bf16(acc[mi][ni], al[mi], bh[ni]);
                }
        }
        __syncthreads();
    }

    // --- epilogue ---
    int rq = lane >> 2, cq = (lane & 3) * 2;
#pragma unroll
    for (int mi = 0; mi < 4; mi++)
#pragma unroll
        for (int hh = 0; hh < 2; hh++) {
            int m = m0 + wm + mi*16 + rq + hh*8;
            int b = m >> 11, s = m & 2047;
#pragma unroll
            for (int ni = 0; ni < 4; ni++) {
                int n = n0 + wn + ni*8 + cq;
                float2 v;
                v.x = acc[mi][ni][hh*2+0] + bias[n];
                v.y = acc[mi][ni][hh*2+1] + bias[n+1];
                if (dstmode) {
                    if (dstmode == 1) { v.x *= 0.125f; v.y *= 0.125f; }
                    __nv_bfloat16* dh = (dstmode == 1) ? g_qhi : (dstmode == 2) ? g_khi : g_vhi;
                    __nv_bfloat16* dl = (dstmode == 1) ? g_qlo : (dstmode == 2) ? g_klo : g_vlo;
                    int h = n >> 6, d = n & 63;
                    size_t idx = (((size_t)(b*NH + h)*SEQ) + s)*HD + d;
                    __nv_bfloat162 h2 = hi2_of(v.x, v.y);
                    *(__nv_bfloat162*)&dh[idx] = h2;
                    *(__nv_bfloat162*)&dl[idx] = lo2_of(v.x, v.y, h2);
                } else {
                    *(float2*)&out[(size_t)m*EMB + n] = v;
                }
            }
        }
}

// ---------------------------------------------------------------------------
// qk_hmma: S[bh][128m][128n] = (Q/8) @ K^T  (3xbf16, K=64)
// ---------------------------------------------------------------------------
#define QKSTR  72
#define QKTILE (128*QKSTR*2)   // 18432
#define QKSMEM (4*QKTILE)      // 73728

__global__ __launch_bounds__(256)
void qk_hmma(float* __restrict__ S)
{
    extern __shared__ char smc[];
    uint32_t smb = smem_u32(smc);
    int tid = threadIdx.x, wid = tid >> 5, lane = tid & 31;
    int bh = blockIdx.z;
    int m0 = blockIdx.y * 128, n0 = blockIdx.x * 128;
    int wm = (wid >> 2) * 64, wn = (wid & 3) * 32;

    const __nv_bfloat16* srcs[4];
    srcs[0] = g_qhi + ((size_t)bh*SEQ + m0) * HD;
    srcs[1] = g_qlo + ((size_t)bh*SEQ + m0) * HD;
    srcs[2] = g_khi + ((size_t)bh*SEQ + n0) * HD;
    srcs[3] = g_klo + ((size_t)bh*SEQ + n0) * HD;

#pragma unroll
    for (int t = 0; t < 4; t++)
#pragma unroll
        for (int h = 0; h < 4; h++) {
            int u = tid + h * 256;
            int row = u >> 3, c8 = (u & 7) * 8;
            cp16(smb + t*QKTILE + (row*QKSTR + c8)*2, srcs[t] + (size_t)row*HD + c8);
        }
    asm volatile("cp.async.commit_group;");
    asm volatile("cp.async.wait_group 0;");
    __syncthreads();

    float acc[4][4][4];
#pragma unroll
    for (int a = 0; a < 4; a++)
#pragma unroll
        for (int b = 0; b < 4; b++)
#pragma unroll
            for (int c = 0; c < 4; c++) acc[a][b][c] = 0.f;

    int r = lane & 7, sel = lane >> 3;
#pragma unroll
    for (int ks = 0; ks < 4; ks++) {
        int k0 = ks * 16;
        int arow = wm + ((sel & 1) ? 8 : 0) + r;
        int acol = k0 + ((sel & 2) ? 8 : 0);
        uint32_t ah[4][4], al[4][4];
#pragma unroll
        for (int mi = 0; mi < 4; mi++) {
            uint32_t ad = smb + (((arow + mi*16) * QKSTR + acol) * 2);
            ldm_x4(ah[mi], ad);
            ldm_x4(al[mi], ad + QKTILE);
        }
        int brow = wn + ((sel & 2) ? 8 : 0) + r;
        int bcol = k0 + ((sel & 1) ? 8 : 0);
        uint32_t bh[4][2], bl[4][2];
#pragma unroll
        for (int p = 0; p < 2; p++) {
            uint32_t t4[4];
            uint32_t bd = smb + 2*QKTILE + (((brow + p*16) * QKSTR + bcol) * 2);
            ldm_x4(t4, bd);
            bh[p*2][0] = t4[0]; bh[p*2][1] = t4[1];
            bh[p*2+1][0] = t4[2]; bh[p*2+1][1] = t4[3];
            ldm_x4(t4, bd + QKTILE);
            bl[p*2][0] = t4[0]; bl[p*2][1] = t4[1];
            bl[p*2+1][0] = t4[2]; bl[p*2+1][1] = t4[3];
        }
#pragma unroll
        for (int mi = 0; mi < 4; mi++)
#pragma unroll
            for (int ni = 0; ni < 4; ni++) {
                mma_bf16(acc[mi][ni], ah[mi], bh[ni]);
                mma_bf16(acc[mi][ni], ah[mi], bl[ni]);
                mma_bf16(acc[mi][ni], al[mi], bh[ni]);
            }
    }

    int rq = lane >> 2, cq = (lane & 3) * 2;
    float* Sp = S + (size_t)bh * SEQ * SEQ;
#pragma unroll
    for (int mi = 0; mi < 4; mi++)
#pragma unroll
        for (int hh = 0; hh < 2; hh++) {
            int m = m0 + wm + mi*16 + rq + hh*8;
#pragma unroll
            for (int ni = 0; ni < 4; ni++) {
                int n = n0 + wn + ni*8 + cq;
                float2 v;
                v.x = acc[mi][ni][hh*2+0];
                v.y = acc[mi][ni][hh*2+1];
                *(float2*)&Sp[(size_t)m*SEQ + n] = v;
            }
        }
}

// ---------------------------------------------------------------------------
// softmax_rows: in-place softmax over rows of 2048 (one warp per row)
// ---------------------------------------------------------------------------
__global__ __launch_bounds__(256)
void softmax_rows(float* __restrict__ S)
{
    size_t row = (size_t)blockIdx.x * 8 + (threadIdx.x >> 5);
    int ln = threadIdx.x & 31;
    float* p = S + row * SEQ;

    float4 v[16];
    float mx = -1e30f;
#pragma unroll
    for (int i = 0; i < 16; i++) {
        v[i] = *(float4*)&p[(i*32 + ln)*4];
        mx = fmaxf(mx, fmaxf(fmaxf(v[i].x, v[i].y), fmaxf(v[i].z, v[i].w)));
    }
#pragma unroll
    for (int m = 1; m < 32; m <<= 1)
        mx = fmaxf(mx, __shfl_xor_sync(0xffffffffu, mx, m));

    float sum = 0.f;
#pragma unroll
    for (int i = 0; i < 16; i++) {
        v[i].x = __expf(v[i].x - mx); v[i].y = __expf(v[i].y - mx);
        v[i].z = __expf(v[i].z - mx); v[i].w = __expf(v[i].w - mx);
        sum += v[i].x + v[i].y + v[i].z + v[i].w;
    }
#pragma unroll
    for (int m = 1; m < 32; m <<= 1)
        sum += __shfl_xor_sync(0xffffffffu, sum, m);
    float inv = 1.f / sum;

#pragma unroll
    for (int i = 0; i < 16; i++) {
        v[i].x *= inv; v[i].y *= inv; v[i].z *= inv; v[i].w *= inv;
        *(float4*)&p[(i*32 + ln)*4] = v[i];
    }
}

// ---------------------------------------------------------------------------
// pv_hmma: O[bh][128m][64d] = P @ V  (P fp32 from S, converted to hi/lo bf16;
// V bf16 hi/lo via ldmatrix.trans). Writes merged attn output to g_xhi/g_xlo.
// ---------------------------------------------------------------------------
#define PVSTR  72
#define PTILE  (128*PVSTR*2)        // 18432
#define VTILE  (64*PVSTR*2)         // 9216
#define PVBUF  (2*PTILE + 2*VTILE)  // 55296
#define PVSMEM (2*PVBUF)            // 110592
#define PVNCH  (SEQ/64)             // 32

__global__ __launch_bounds__(256)
void pv_hmma(const float* __restrict__ S)
{
    extern __shared__ char smc[];
    uint32_t smb = smem_u32(smc);
    int tid = threadIdx.x, wid = tid >> 5, lane = tid & 31;
    int bh = blockIdx.y;
    int m0 = blockIdx.x * 128;
    int wm = (wid >> 2) * 64, wn = (wid & 3) * 16;

    const float* Sp = S + ((size_t)bh*SEQ + m0) * SEQ;
    const __nv_bfloat16* Vh = g_vhi + (size_t)bh * SEQ * HD;
    const __nv_bfloat16* Vl = g_vlo + (size_t)bh * SEQ * HD;

    float acc[4][2][4];
#pragma unroll
    for (int a = 0; a < 4; a++)
#pragma unroll
        for (int b = 0; b < 2; b++)
#pragma unroll
            for (int c = 0; c < 4; c++) acc[a][b][c] = 0.f;

    float4 pr[8];

    // ---- prologue: chunk 0 ----
#pragma unroll
    for (int i = 0; i < 8; i++) {
        int u = tid + i * 256;
        int row = u >> 4, c4 = (u & 15) * 4;
        pr[i] = *(const float4*)&Sp[(size_t)row*SEQ + c4];
    }
#pragma unroll
    for (int t = 0; t < 2; t++) {
        const __nv_bfloat16* src = t ? Vl : Vh;
#pragma unroll
        for (int i = 0; i < 2; i++) {
            int u = tid + i * 256;
            int row = u >> 3, c8 = (u & 7) * 8;
            cp16(smb + 2*PTILE + t*VTILE + (row*PVSTR + c8)*2,
                 src + (size_t)row*HD + c8);
        }
    }
    // convert & store P chunk 0 to buf0
#pragma unroll
    for (int i = 0; i < 8; i++) {
        int u = tid + i * 256;
        int row = u >> 4, c4 = (u & 15) * 4;
        __nv_bfloat162 hA = hi2_of(pr[i].x, pr[i].y);
        __nv_bfloat162 hB = hi2_of(pr[i].z, pr[i].w);
        __nv_bfloat162 lA = lo2_of(pr[i].x, pr[i].y, hA);
        __nv_bfloat162 lB = lo2_of(pr[i].z, pr[i].w, hB);
        char* ph = smc + (row*PVSTR + c4)*2;
        ((__nv_bfloat162*)ph)[0] = hA; ((__nv_bfloat162*)ph)[1] = hB;
        char* pl = ph + PTILE;
        ((__nv_bfloat162*)pl)[0] = lA; ((__nv_bfloat162*)pl)[1] = lB;
    }
    asm volatile("cp.async.commit_group;");

    int r = lane & 7, sel = lane >> 3;

    for (int c = 0; c < PVNCH; c++) {
        int buf = c & 1;
        asm volatile("cp.async.wait_group 0;");
        __syncthreads();

        if (c + 1 < PVNCH) {
            // issue global loads for next P chunk + cp.async next V chunk
#pragma unroll
            for (int i = 0; i < 8; i++) {
                int u = tid + i * 256;
                int row = u >> 4, c4 = (u & 15) * 4;
                pr[i] = *(const float4*)&Sp[(size_t)row*SEQ + (c+1)*64 + c4];
            }
#pragma unroll
            for (int t = 0; t < 2; t++) {
                const __nv_bfloat16* src = (t ? Vl : Vh) + (size_t)(c+1)*64*HD;
#pragma unroll
                for (int i = 0; i < 2; i++) {
                    int u = tid + i * 256;
                    int row = u >> 3, c8 = (u & 7) * 8;
                    cp16(smb + (buf^1)*PVBUF + 2*PTILE + t*VTILE + (row*PVSTR + c8)*2,
                         src + (size_t)row*HD + c8);
                }
            }
            asm volatile("cp.async.commit_group;");
        }

        // ---- MMA on current buffer ----
        uint32_t pbase = smb + buf * PVBUF;
#pragma unroll
        for (int ks = 0; ks < 4; ks++) {
            int k0 = ks * 16;
            int arow = wm + ((sel & 1) ? 8 : 0) + r;
            int acol = k0 + ((sel & 2) ? 8 : 0);
            uint32_t ah[4][4], al[4][4];
#pragma unroll
            for (int mi = 0; mi < 4; mi++) {
                uint32_t ad = pbase + (((arow + mi*16) * PVSTR + acol) * 2);
                ldm_x4(ah[mi], ad);
                ldm_x4(al[mi], ad + PTILE);
            }
            // B via ldmatrix.trans from V stored [k][n]
            int krow = k0 + ((sel & 1) ? 8 : 0) + r;
            int ncol = wn + ((sel & 2) ? 8 : 0);
            uint32_t bhf[2][2], blf[2][2], t4[4];
            uint32_t bd = pbase + 2*PTILE + ((krow * PVSTR + ncol) * 2);
            ldm_x4_t(t4, bd);
            bhf[0][0] = t4[0]; bhf[0][1] = t4[1];
            bhf[1][0] = t4[2]; bhf[1][1] = t4[3];
            ldm_x4_t(t4, bd + VTILE);
            blf[0][0] = t4[0]; blf[0][1] = t4[1];
            blf[1][0] = t4[2]; blf[1][1] = t4[3];
#pragma unroll
            for (int mi = 0; mi < 4; mi++)
#pragma unroll
                for (int ni = 0; ni < 2; ni++) {
                    mma_bf16(acc[mi][ni], ah[mi], bhf[ni]);
                    mma_bf16(acc[mi][ni], ah[mi], blf[ni]);
                    mma_bf16(acc[mi][ni], al[mi], bhf[ni]);
                }
        }

        if (c + 1 < PVNCH) {
            // convert & store next P chunk into other buffer
#pragma unroll
            for (int i = 0; i < 8; i++) {
                int u = tid + i * 256;
                int row = u >> 4, c4 = (u & 15) * 4;
                __nv_bfloat162 hA = hi2_of(pr[i].x, pr[i].y);
                __nv_bfloat162 hB = hi2_of(pr[i].z, pr[i].w);
                __nv_bfloat162 lA = lo2_of(pr[i].x, pr[i].y, hA);
                __nv_bfloat162 lB = lo2_of(pr[i].z, pr[i].w, hB);
                char* ph = smc + (buf^1)*PVBUF + (row*PVSTR + c4)*2;
                ((__nv_bfloat162*)ph)[0] = hA; ((__nv_bfloat162*)ph)[1] = hB;
                char* pl = ph + PTILE;
                ((__nv_bfloat162*)pl)[0] = lA; ((__nv_bfloat162*)pl)[1] = lB;
            }
        }
    }

    // ---- epilogue: write merged attn output as bf16 hi/lo for final GEMM ----
    int rq = lane >> 2, cq = (lane & 3) * 2;
    int b = bh >> 4, h = bh & 15;
#pragma unroll
    for (int mi = 0; mi < 4; mi++)
#pragma unroll
        for (int hh = 0; hh < 2; hh++) {
            int s = m0 + wm + mi*16 + rq + hh*8;
#pragma unroll
            for (int ni = 0; ni < 2; ni++) {
                int d = wn + ni*8 + cq;
                float vx = acc[mi][ni][hh*2+0];
                float vy = acc[mi][ni][hh*2+1];
                size_t idx = ((size_t)(b*SEQ + s))*EMB + h*HD + d;
                __nv_bfloat162 h2 = hi2_of(vx, vy);
                *(__nv_bfloat162*)&g_xhi[idx] = h2;
                *(__nv_bfloat162*)&g_xlo[idx] = lo2_of(vx, vy, h2);
            }
        }
}

// ---------------------------------------------------------------------------
extern "C" void kernel_launch(void* const* d_in, const int* in_sizes, int n_in,
                              void* d_out, int out_size)
{
    const float* x  = (const float*)d_in[0];
    const float* bq = (const float*)d_in[5];
    const float* bk = (const float*)d_in[6];
    const float* bv = (const float*)d_in[7];
    const float* bo = (const float*)d_in[8];
    float* out = (float*)d_out;

    float* attnW = (out_size >= (OUT0_ELEMS + OUT1_ELEMS)) ? (out + OUT0_ELEMS)
                                                           : (float*)0;
    float* Sbuf = attnW;
    if (!Sbuf) {
        cudaMemcpyAsync(&Sbuf, 0, 0, cudaMemcpyDeviceToDevice); // no-op keep
        void* p = 0;
        cudaGetSymbolAddress(&p, g_s_fallback);
        Sbuf = (float*)p;
    }

    cudaFuncSetAttribute(gemm_hmma,
                         cudaFuncAttributeMaxDynamicSharedMemorySize, GSMEM);
    cudaFuncSetAttribute(qk_hmma,
                         cudaFuncAttributeMaxDynamicSharedMemorySize, QKSMEM);
    cudaFuncSetAttribute(pv_hmma,
                         cudaFuncAttributeMaxDynamicSharedMemorySize, PVSMEM);

    // Split weights (transposed) and x into bf16 hi/lo
    split_w<<<dim3(32, 32, 4), dim3(32, 32)>>>(
        (const float*)d_in[1], (const float*)d_in[2],
        (const float*)d_in[3], (const float*)d_in[4]);
    split_x<<<MROWS*EMB/(256*4), 256>>>(x);

    dim3 gg(EMB/128, MROWS/128);   // (8, 64)
    gemm_hmma<<<gg, 256, GSMEM>>>(bq, (float*)0, 0, 1);
    gemm_hmma<<<gg, 256, GSMEM>>>(bk, (float*)0, 1, 2);
    gemm_hmma<<<gg, 256, GSMEM>>>(bv, (float*)0, 2, 3);

    qk_hmma<<<dim3(SEQ/128, SEQ/128, BATCH*NH), 256, QKSMEM>>>(Sbuf);
    softmax_rows<<<(BATCH*NH*SEQ)/8, 256>>>(Sbuf);
    pv_hmma<<<dim3(SEQ/128, BATCH*NH), 256, PVSMEM>>>(Sbuf);

    gemm_hmma<<<gg, 256, GSMEM>>>(bo, out, 3, 0);
}

// round 6
// speedup vs baseline: 4.2370x; 1.1646x over previous
#include <cuda_runtime.h>
#include <cuda_bf16.h>
#include <stdint.h>

// ---------------------------------------------------------------------------
// Problem constants
// ---------------------------------------------------------------------------
#define EMB   1024
#define NH    16
#define HD    64
#define BATCH 4
#define SEQ   2048
#define MROWS (BATCH*SEQ)              // 8192
#define OUT0_ELEMS (MROWS*EMB)         // 8388608  (output)
#define OUT1_ELEMS (BATCH*NH*SEQ*SEQ)  // 268435456 (attn_weights)
#define NROWS (BATCH*NH*SEQ)           // 131072 attention rows
#define NTILE (SEQ/128)                // 16 col-tiles per row

// Scratch (allocation-free: __device__ globals)
__device__ __nv_bfloat16 g_xhi[MROWS*EMB];
__device__ __nv_bfloat16 g_xlo[MROWS*EMB];
__device__ __nv_bfloat16 g_wthi[4*EMB*EMB];   // transposed weights [w][n][k]
__device__ __nv_bfloat16 g_wtlo[4*EMB*EMB];
__device__ __nv_bfloat16 g_qhi[BATCH*NH*SEQ*HD];
__device__ __nv_bfloat16 g_qlo[BATCH*NH*SEQ*HD];
__device__ __nv_bfloat16 g_khi[BATCH*NH*SEQ*HD];
__device__ __nv_bfloat16 g_klo[BATCH*NH*SEQ*HD];
__device__ __nv_bfloat16 g_vhi[BATCH*NH*SEQ*HD];
__device__ __nv_bfloat16 g_vlo[BATCH*NH*SEQ*HD];
__device__ float  g_tmax[NROWS*NTILE];
__device__ float  g_tsum[NROWS*NTILE];
__device__ float2 g_rowstat[NROWS];
__device__ float  g_s_fallback[OUT1_ELEMS];   // used only if attnW not in d_out

// ---------------------------------------------------------------------------
// helpers
// ---------------------------------------------------------------------------
__device__ __forceinline__ uint32_t smem_u32(const void* p) {
    uint32_t a;
    asm("{ .reg .u64 t; cvta.to.shared.u64 t, %1; cvt.u32.u64 %0, t; }"
        : "=r"(a) : "l"(p));
    return a;
}
__device__ __forceinline__ void ldm_x4(uint32_t* r, uint32_t addr) {
    asm volatile("ldmatrix.sync.aligned.m8n8.x4.shared.b16 {%0,%1,%2,%3}, [%4];"
        : "=r"(r[0]), "=r"(r[1]), "=r"(r[2]), "=r"(r[3]) : "r"(addr));
}
__device__ __forceinline__ void ldm_x4_t(uint32_t* r, uint32_t addr) {
    asm volatile("ldmatrix.sync.aligned.m8n8.x4.trans.shared.b16 {%0,%1,%2,%3}, [%4];"
        : "=r"(r[0]), "=r"(r[1]), "=r"(r[2]), "=r"(r[3]) : "r"(addr));
}
__device__ __forceinline__ void mma_bf16(float* c, const uint32_t* a, const uint32_t* b) {
    asm volatile("mma.sync.aligned.m16n8k16.row.col.f32.bf16.bf16.f32 "
        "{%0,%1,%2,%3}, {%4,%5,%6,%7}, {%8,%9}, {%0,%1,%2,%3};"
        : "+f"(c[0]), "+f"(c[1]), "+f"(c[2]), "+f"(c[3])
        : "r"(a[0]), "r"(a[1]), "r"(a[2]), "r"(a[3]), "r"(b[0]), "r"(b[1]));
}
__device__ __forceinline__ void cp16(uint32_t saddr, const void* gaddr) {
    asm volatile("cp.async.cg.shared.global [%0], [%1], 16;" :: "r"(saddr), "l"(gaddr));
}
__device__ __forceinline__ __nv_bfloat162 hi2_of(float x, float y) {
    __nv_bfloat162 h; h.x = __float2bfloat16(x); h.y = __float2bfloat16(y);
    return h;
}
__device__ __forceinline__ __nv_bfloat162 lo2_of(float x, float y, __nv_bfloat162 h) {
    __nv_bfloat162 l;
    l.x = __float2bfloat16(x - __bfloat162float(h.x));
    l.y = __float2bfloat16(y - __bfloat162float(h.y));
    return l;
}

// ---------------------------------------------------------------------------
// split kernels: fp32 -> bf16 hi/lo
// ---------------------------------------------------------------------------
__global__ void split_w(const float* __restrict__ wq, const float* __restrict__ wk,
                        const float* __restrict__ wv, const float* __restrict__ wo)
{
    __shared__ float t[32][33];
    int z = blockIdx.z;
    const float* W = (z == 0) ? wq : (z == 1) ? wk : (z == 2) ? wv : wo;
    int n0 = blockIdx.x * 32, k0 = blockIdx.y * 32;
    int tx = threadIdx.x, ty = threadIdx.y;
    t[ty][tx] = W[(size_t)(k0 + ty) * EMB + n0 + tx];
    __syncthreads();
    float v = t[tx][ty];                        // = W[k0+tx][n0+ty]
    __nv_bfloat16 hi = __float2bfloat16(v);
    __nv_bfloat16 lo = __float2bfloat16(v - __bfloat162float(hi));
    size_t o = (size_t)z * (EMB*EMB) + (size_t)(n0 + ty) * EMB + (k0 + tx);
    g_wthi[o] = hi;
    g_wtlo[o] = lo;
}

__global__ void split_x(const float* __restrict__ src)
{
    int i = (blockIdx.x * 256 + threadIdx.x) * 4;
    float4 v = *(const float4*)&src[i];
    __nv_bfloat162 hA = hi2_of(v.x, v.y);
    __nv_bfloat162 hB = hi2_of(v.z, v.w);
    *(__nv_bfloat162*)&g_xhi[i]   = hA;
    *(__nv_bfloat162*)&g_xhi[i+2] = hB;
    *(__nv_bfloat162*)&g_xlo[i]   = lo2_of(v.x, v.y, hA);
    *(__nv_bfloat162*)&g_xlo[i+2] = lo2_of(v.z, v.w, hB);
}

// ---------------------------------------------------------------------------
// HMMA 3xbf16 GEMM: C[8192,1024] = (xhi+xlo) @ (Wt hi+lo)^T + bias
// dstmode 0: fp32 -> out [M][E]
// dstmode 1/2/3: bf16 hi/lo -> g_q/g_k/g_v (Q scaled by 1/8, exact)
// ---------------------------------------------------------------------------
#define KC       32
#define NCH      (EMB/KC)          // 32
#define TSTRIDE  40                // bf16 elems per smem row (80B, conflict-free)
#define TILE_B   (128*TSTRIDE*2)   // 10240 bytes
#define BUF_B    (4*TILE_B)        // Ahi, Alo, Bhi, Blo
#define GSMEM    (2*BUF_B)         // 81920

__global__ __launch_bounds__(256)
void gemm_hmma(const float* __restrict__ bias, float* __restrict__ out,
               int widx, int dstmode)
{
    extern __shared__ char smc[];
    uint32_t smb = smem_u32(smc);
    int tid = threadIdx.x, wid = tid >> 5, lane = tid & 31;
    int m0 = blockIdx.y * 128, n0 = blockIdx.x * 128;
    int wm = (wid >> 2) * 64, wn = (wid & 3) * 32;

    const __nv_bfloat16* srcs[4];
    srcs[0] = g_xhi + (size_t)m0 * EMB;
    srcs[1] = g_xlo + (size_t)m0 * EMB;
    srcs[2] = g_wthi + (size_t)widx * (EMB*EMB) + (size_t)n0 * EMB;
    srcs[3] = g_wtlo + (size_t)widx * (EMB*EMB) + (size_t)n0 * EMB;

    float acc[4][4][4];
#pragma unroll
    for (int a = 0; a < 4; a++)
#pragma unroll
        for (int b = 0; b < 4; b++)
#pragma unroll
            for (int c = 0; c < 4; c++) acc[a][b][c] = 0.f;

    // --- prefetch chunk 0 ---
    {
#pragma unroll
        for (int t = 0; t < 4; t++)
#pragma unroll
            for (int h = 0; h < 2; h++) {
                int s = tid + h * 256;
                int row = s >> 2, c8 = (s & 3) * 8;
                cp16(smb + t*TILE_B + (row*TSTRIDE + c8)*2,
                     srcs[t] + (size_t)row * EMB + c8);
            }
        asm volatile("cp.async.commit_group;");
    }

    for (int kc = 0; kc < NCH; kc++) {
        int buf = kc & 1;
        if (kc + 1 < NCH) {
            int nb = (kc + 1) & 1;
#pragma unroll
            for (int t = 0; t < 4; t++)
#pragma unroll
                for (int h = 0; h < 2; h++) {
                    int s = tid + h * 256;
                    int row = s >> 2, c8 = (s & 3) * 8;
                    cp16(smb + nb*BUF_B + t*TILE_B + (row*TSTRIDE + c8)*2,
                         srcs[t] + (size_t)row * EMB + (kc+1)*KC + c8);
                }
            asm volatile("cp.async.commit_group;");
            asm volatile("cp.async.wait_group 1;");
        } else {
            asm volatile("cp.async.wait_group 0;");
        }
        __syncthreads();

        uint32_t base = smb + buf * BUF_B;
        int r = lane & 7, sel = lane >> 3;
#pragma unroll
        for (int ks = 0; ks < 2; ks++) {
            int k0 = ks * 16;
            int arow = wm + ((sel & 1) ? 8 : 0) + r;
            int acol = k0 + ((sel & 2) ? 8 : 0);
            uint32_t ah[4][4], al[4][4];
#pragma unroll
            for (int mi = 0; mi < 4; mi++) {
                uint32_t ad = base + (((arow + mi*16) * TSTRIDE + acol) * 2);
                ldm_x4(ah[mi], ad);
                ldm_x4(al[mi], ad + TILE_B);
            }
            int brow = wn + ((sel & 2) ? 8 : 0) + r;
            int bcol = k0 + ((sel & 1) ? 8 : 0);
            uint32_t bh[4][2], bl[4][2];
#pragma unroll
            for (int p = 0; p < 2; p++) {
                uint32_t t4[4];
                uint32_t bd = base + 2*TILE_B + (((brow + p*16) * TSTRIDE + bcol) * 2);
                ldm_x4(t4, bd);
                bh[p*2][0] = t4[0]; bh[p*2][1] = t4[1];
                bh[p*2+1][0] = t4[2]; bh[p*2+1][1] = t4[3];
                ldm_x4(t4, bd + TILE_B);
                bl[p*2][0] = t4[0]; bl[p*2][1] = t4[1];
                bl[p*2+1][0] = t4[2]; bl[p*2+1][1] = t4[3];
            }
#pragma unroll
            for (int mi = 0; mi < 4; mi++)
#pragma unroll
                for (int ni = 0; ni < 4; ni++) {
                    mma_bf16(acc[mi][ni], ah[mi], bh[ni]);
                    mma_bf16(acc[mi][ni], ah[mi], bl[ni]);
                    mma_bf16(acc[mi][ni], al[mi], bh[ni]);
                }
        }
        __syncthreads();
    }

    // --- epilogue ---
    int rq = lane >> 2, cq = (lane & 3) * 2;
#pragma unroll
    for (int mi = 0; mi < 4; mi++)
#pragma unroll
        for (int hh = 0; hh < 2; hh++) {
            int m = m0 + wm + mi*16 + rq + hh*8;
            int b = m >> 11, s = m & 2047;
#pragma unroll
            for (int ni = 0; ni < 4; ni++) {
                int n = n0 + wn + ni*8 + cq;
                float2 v;
                v.x = acc[mi][ni][hh*2+0] + bias[n];
                v.y = acc[mi][ni][hh*2+1] + bias[n+1];
                if (dstmode) {
                    if (dstmode == 1) { v.x *= 0.125f; v.y *= 0.125f; }
                    __nv_bfloat16* dh = (dstmode == 1) ? g_qhi : (dstmode == 2) ? g_khi : g_vhi;
                    __nv_bfloat16* dl = (dstmode == 1) ? g_qlo : (dstmode == 2) ? g_klo : g_vlo;
                    int h = n >> 6, d = n & 63;
                    size_t idx = (((size_t)(b*NH + h)*SEQ) + s)*HD + d;
                    __nv_bfloat162 h2 = hi2_of(v.x, v.y);
                    *(__nv_bfloat162*)&dh[idx] = h2;
                    *(__nv_bfloat162*)&dl[idx] = lo2_of(v.x, v.y, h2);
                } else {
                    *(float2*)&out[(size_t)m*EMB + n] = v;
                }
            }
        }
}

// ---------------------------------------------------------------------------
// qk_hmma: S[bh][128m][128n] = (Q/8) @ K^T  (3xbf16, K=64)
// Also emits per-(row, n-tile) max and sum-exp stats.
// ---------------------------------------------------------------------------
#define QKSTR  72
#define QKTILE (128*QKSTR*2)   // 18432
#define QKSMEM (4*QKTILE)      // 73728

__global__ __launch_bounds__(256)
void qk_hmma(float* __restrict__ S)
{
    extern __shared__ char smc[];
    uint32_t smb = smem_u32(smc);
    int tid = threadIdx.x, wid = tid >> 5, lane = tid & 31;
    int bh = blockIdx.z;
    int m0 = blockIdx.y * 128, n0 = blockIdx.x * 128;
    int wm = (wid >> 2) * 64, wn = (wid & 3) * 32;

    const __nv_bfloat16* srcs[4];
    srcs[0] = g_qhi + ((size_t)bh*SEQ + m0) * HD;
    srcs[1] = g_qlo + ((size_t)bh*SEQ + m0) * HD;
    srcs[2] = g_khi + ((size_t)bh*SEQ + n0) * HD;
    srcs[3] = g_klo + ((size_t)bh*SEQ + n0) * HD;

#pragma unroll
    for (int t = 0; t < 4; t++)
#pragma unroll
        for (int h = 0; h < 4; h++) {
            int u = tid + h * 256;
            int row = u >> 3, c8 = (u & 7) * 8;
            cp16(smb + t*QKTILE + (row*QKSTR + c8)*2, srcs[t] + (size_t)row*HD + c8);
        }
    asm volatile("cp.async.commit_group;");
    asm volatile("cp.async.wait_group 0;");
    __syncthreads();

    float acc[4][4][4];
#pragma unroll
    for (int a = 0; a < 4; a++)
#pragma unroll
        for (int b = 0; b < 4; b++)
#pragma unroll
            for (int c = 0; c < 4; c++) acc[a][b][c] = 0.f;

    int r = lane & 7, sel = lane >> 3;
#pragma unroll
    for (int ks = 0; ks < 4; ks++) {
        int k0 = ks * 16;
        int arow = wm + ((sel & 1) ? 8 : 0) + r;
        int acol = k0 + ((sel & 2) ? 8 : 0);
        uint32_t ah[4][4], al[4][4];
#pragma unroll
        for (int mi = 0; mi < 4; mi++) {
            uint32_t ad = smb + (((arow + mi*16) * QKSTR + acol) * 2);
            ldm_x4(ah[mi], ad);
            ldm_x4(al[mi], ad + QKTILE);
        }
        int brow = wn + ((sel & 2) ? 8 : 0) + r;
        int bcol = k0 + ((sel & 1) ? 8 : 0);
        uint32_t bh[4][2], bl[4][2];
#pragma unroll
        for (int p = 0; p < 2; p++) {
            uint32_t t4[4];
            uint32_t bd = smb + 2*QKTILE + (((brow + p*16) * QKSTR + bcol) * 2);
            ldm_x4(t4, bd);
            bh[p*2][0] = t4[0]; bh[p*2][1] = t4[1];
            bh[p*2+1][0] = t4[2]; bh[p*2+1][1] = t4[3];
            ldm_x4(t4, bd + QKTILE);
            bl[p*2][0] = t4[0]; bl[p*2][1] = t4[1];
            bl[p*2+1][0] = t4[2]; bl[p*2+1][1] = t4[3];
        }
#pragma unroll
        for (int mi = 0; mi < 4; mi++)
#pragma unroll
            for (int ni = 0; ni < 4; ni++) {
                mma_bf16(acc[mi][ni], ah[mi], bh[ni]);
                mma_bf16(acc[mi][ni], ah[mi], bl[ni]);
                mma_bf16(acc[mi][ni], al[mi], bh[ni]);
            }
    }

    int rq = lane >> 2, cq = (lane & 3) * 2;
    float* Sp = S + (size_t)bh * SEQ * SEQ;
#pragma unroll
    for (int mi = 0; mi < 4; mi++)
#pragma unroll
        for (int hh = 0; hh < 2; hh++) {
            int m = m0 + wm + mi*16 + rq + hh*8;
#pragma unroll
            for (int ni = 0; ni < 4; ni++) {
                int n = n0 + wn + ni*8 + cq;
                float2 v;
                v.x = acc[mi][ni][hh*2+0];
                v.y = acc[mi][ni][hh*2+1];
                *(float2*)&Sp[(size_t)m*SEQ + n] = v;
            }
        }

    // ---- per-(row, tile) softmax stats ----
    __syncthreads();                      // all smem tile reads done; reuse smc
    float* st = (float*)smc;              // [128][4][2]
    int wq4 = wid & 3;
#pragma unroll
    for (int mi = 0; mi < 4; mi++)
#pragma unroll
        for (int hh = 0; hh < 2; hh++) {
            float m8 = -1e30f;
#pragma unroll
            for (int ni = 0; ni < 4; ni++)
                m8 = fmaxf(m8, fmaxf(acc[mi][ni][hh*2+0], acc[mi][ni][hh*2+1]));
            m8 = fmaxf(m8, __shfl_xor_sync(0xffffffffu, m8, 1));
            m8 = fmaxf(m8, __shfl_xor_sync(0xffffffffu, m8, 2));
            float s8 = 0.f;
#pragma unroll
            for (int ni = 0; ni < 4; ni++)
                s8 += __expf(acc[mi][ni][hh*2+0] - m8) + __expf(acc[mi][ni][hh*2+1] - m8);
            s8 += __shfl_xor_sync(0xffffffffu, s8, 1);
            s8 += __shfl_xor_sync(0xffffffffu, s8, 2);
            if ((lane & 3) == 0) {
                int rl = wm + mi*16 + rq + hh*8;
                st[(rl*4 + wq4)*2 + 0] = m8;
                st[(rl*4 + wq4)*2 + 1] = s8;
            }
        }
    __syncthreads();
    if (tid < 128) {
        float m = -1e30f;
#pragma unroll
        for (int j = 0; j < 4; j++) m = fmaxf(m, st[(tid*4 + j)*2]);
        float s = 0.f;
#pragma unroll
        for (int j = 0; j < 4; j++)
            s += st[(tid*4 + j)*2 + 1] * __expf(st[(tid*4 + j)*2] - m);
        size_t o = ((size_t)bh*SEQ + m0 + tid) * NTILE + blockIdx.x;
        g_tmax[o] = m;
        g_tsum[o] = s;
    }
}

// ---------------------------------------------------------------------------
// rowstat_combine: per attention row -> (global max, 1/sum)
// ---------------------------------------------------------------------------
__global__ __launch_bounds__(256)
void rowstat_combine()
{
    int row = blockIdx.x * 256 + threadIdx.x;
    const float* tm = &g_tmax[(size_t)row * NTILE];
    const float* ts = &g_tsum[(size_t)row * NTILE];
    float m = -1e30f;
#pragma unroll
    for (int t = 0; t < NTILE; t++) m = fmaxf(m, tm[t]);
    float s = 0.f;
#pragma unroll
    for (int t = 0; t < NTILE; t++) s += ts[t] * __expf(tm[t] - m);
    g_rowstat[row] = make_float2(m, 1.f / s);
}

// ---------------------------------------------------------------------------
// pv_hmma: reads raw S, applies softmax (p = exp(s-gmax)*inv) on the fly,
// writes normalized P back to attnW in place, computes O = P @ V (3xbf16).
// Writes merged attn output to g_xhi/g_xlo for the final projection.
// ---------------------------------------------------------------------------
#define PVSTR  72
#define PTILE  (128*PVSTR*2)        // 18432
#define VTILE  (64*PVSTR*2)         // 9216
#define PVBUF  (2*PTILE + 2*VTILE)  // 55296
#define PVSMEM (2*PVBUF)            // 110592
#define PVNCH  (SEQ/64)             // 32

__global__ __launch_bounds__(256)
void pv_hmma(float* __restrict__ S)
{
    extern __shared__ char smc[];
    __shared__ float2 rs[128];
    uint32_t smb = smem_u32(smc);
    int tid = threadIdx.x, wid = tid >> 5, lane = tid & 31;
    int bh = blockIdx.y;
    int m0 = blockIdx.x * 128;
    int wm = (wid >> 2) * 64, wn = (wid & 3) * 16;

    float* Sp = S + ((size_t)bh*SEQ + m0) * SEQ;
    const __nv_bfloat16* Vh = g_vhi + (size_t)bh * SEQ * HD;
    const __nv_bfloat16* Vl = g_vlo + (size_t)bh * SEQ * HD;

    if (tid < 128) rs[tid] = g_rowstat[(size_t)bh*SEQ + m0 + tid];
    __syncthreads();

    float acc[4][2][4];
#pragma unroll
    for (int a = 0; a < 4; a++)
#pragma unroll
        for (int b = 0; b < 2; b++)
#pragma unroll
            for (int c = 0; c < 4; c++) acc[a][b][c] = 0.f;

    float4 pr[8];

    // ---- prologue: chunk 0 ----
#pragma unroll
    for (int i = 0; i < 8; i++) {
        int u = tid + i * 256;
        int row = u >> 4, c4 = (u & 15) * 4;
        pr[i] = *(const float4*)&Sp[(size_t)row*SEQ + c4];
    }
#pragma unroll
    for (int t = 0; t < 2; t++) {
        const __nv_bfloat16* src = t ? Vl : Vh;
#pragma unroll
        for (int i = 0; i < 2; i++) {
            int u = tid + i * 256;
            int row = u >> 3, c8 = (u & 7) * 8;
            cp16(smb + 2*PTILE + t*VTILE + (row*PVSTR + c8)*2,
                 src + (size_t)row*HD + c8);
        }
    }
    // softmax + convert & store P chunk 0 to buf0, write normalized P
#pragma unroll
    for (int i = 0; i < 8; i++) {
        int u = tid + i * 256;
        int row = u >> 4, c4 = (u & 15) * 4;
        float gm = rs[row].x, inv = rs[row].y;
        float4 p;
        p.x = __expf(pr[i].x - gm) * inv;
        p.y = __expf(pr[i].y - gm) * inv;
        p.z = __expf(pr[i].z - gm) * inv;
        p.w = __expf(pr[i].w - gm) * inv;
        *(float4*)&Sp[(size_t)row*SEQ + c4] = p;
        __nv_bfloat162 hA = hi2_of(p.x, p.y);
        __nv_bfloat162 hB = hi2_of(p.z, p.w);
        __nv_bfloat162 lA = lo2_of(p.x, p.y, hA);
        __nv_bfloat162 lB = lo2_of(p.z, p.w, hB);
        char* ph = smc + (row*PVSTR + c4)*2;
        ((__nv_bfloat162*)ph)[0] = hA; ((__nv_bfloat162*)ph)[1] = hB;
        char* pl = ph + PTILE;
        ((__nv_bfloat162*)pl)[0] = lA; ((__nv_bfloat162*)pl)[1] = lB;
    }
    asm volatile("cp.async.commit_group;");

    int r = lane & 7, sel = lane >> 3;

    for (int c = 0; c < PVNCH; c++) {
        int buf = c & 1;
        asm volatile("cp.async.wait_group 0;");
        __syncthreads();

        if (c + 1 < PVNCH) {
            // issue global loads for next P chunk + cp.async next V chunk
#pragma unroll
            for (int i = 0; i < 8; i++) {
                int u = tid + i * 256;
                int row = u >> 4, c4 = (u & 15) * 4;
                pr[i] = *(const float4*)&Sp[(size_t)row*SEQ + (c+1)*64 + c4];
            }
#pragma unroll
            for (int t = 0; t < 2; t++) {
                const __nv_bfloat16* src = (t ? Vl : Vh) + (size_t)(c+1)*64*HD;
#pragma unroll
                for (int i = 0; i < 2; i++) {
                    int u = tid + i * 256;
                    int row = u >> 3, c8 = (u & 7) * 8;
                    cp16(smb + (buf^1)*PVBUF + 2*PTILE + t*VTILE + (row*PVSTR + c8)*2,
                         src + (size_t)row*HD + c8);
                }
            }
            asm volatile("cp.async.commit_group;");
        }

        // ---- MMA on current buffer ----
        uint32_t pbase = smb + buf * PVBUF;
#pragma unroll
        for (int ks = 0; ks < 4; ks++) {
            int k0 = ks * 16;
            int arow = wm + ((sel & 1) ? 8 : 0) + r;
            int acol = k0 + ((sel & 2) ? 8 : 0);
            uint32_t ah[4][4], al[4][4];
#pragma unroll
            for (int mi = 0; mi < 4; mi++) {
                uint32_t ad = pbase + (((arow + mi*16) * PVSTR + acol) * 2);
                ldm_x4(ah[mi], ad);
                ldm_x4(al[mi], ad + PTILE);
            }
            // B via ldmatrix.trans from V stored [k][n]
            int krow = k0 + ((sel & 1) ? 8 : 0) + r;
            int ncol = wn + ((sel & 2) ? 8 : 0);
            uint32_t bhf[2][2], blf[2][2], t4[4];
            uint32_t bd = pbase + 2*PTILE + ((krow * PVSTR + ncol) * 2);
            ldm_x4_t(t4, bd);
            bhf[0][0] = t4[0]; bhf[0][1] = t4[1];
            bhf[1][0] = t4[2]; bhf[1][1] = t4[3];
            ldm_x4_t(t4, bd + VTILE);
            blf[0][0] = t4[0]; blf[0][1] = t4[1];
            blf[1][0] = t4[2]; blf[1][1] = t4[3];
#pragma unroll
            for (int mi = 0; mi < 4; mi++)
#pragma unroll
                for (int ni = 0; ni < 2; ni++) {
                    mma_bf16(acc[mi][ni], ah[mi], bhf[ni]);
                    mma_bf16(acc[mi][ni], ah[mi], blf[ni]);
                    mma_bf16(acc[mi][ni], al[mi], bhf[ni]);
                }
        }

        if (c + 1 < PVNCH) {
            // softmax + convert & store next P chunk into other buffer
#pragma unroll
            for (int i = 0; i < 8; i++) {
                int u = tid + i * 256;
                int row = u >> 4, c4 = (u & 15) * 4;
                float gm = rs[row].x, inv = rs[row].y;
                float4 p;
                p.x = __expf(pr[i].x - gm) * inv;
                p.y = __expf(pr[i].y - gm) * inv;
                p.z = __expf(pr[i].z - gm) * inv;
                p.w = __expf(pr[i].w - gm) * inv;
                *(float4*)&Sp[(size_t)row*SEQ + (c+1)*64 + c4] = p;
                __nv_bfloat162 hA = hi2_of(p.x, p.y);
                __nv_bfloat162 hB = hi2_of(p.z, p.w);
                __nv_bfloat162 lA = lo2_of(p.x, p.y, hA);
                __nv_bfloat162 lB = lo2_of(p.z, p.w, hB);
                char* ph = smc + (buf^1)*PVBUF + (row*PVSTR + c4)*2;
                ((__nv_bfloat162*)ph)[0] = hA; ((__nv_bfloat162*)ph)[1] = hB;
                char* pl = ph + PTILE;
                ((__nv_bfloat162*)pl)[0] = lA; ((__nv_bfloat162*)pl)[1] = lB;
            }
        }
    }

    // ---- epilogue: write merged attn output as bf16 hi/lo for final GEMM ----
    int rq = lane >> 2, cq = (lane & 3) * 2;
    int b = bh >> 4, h = bh & 15;
#pragma unroll
    for (int mi = 0; mi < 4; mi++)
#pragma unroll
        for (int hh = 0; hh < 2; hh++) {
            int s = m0 + wm + mi*16 + rq + hh*8;
#pragma unroll
            for (int ni = 0; ni < 2; ni++) {
                int d = wn + ni*8 + cq;
                float vx = acc[mi][ni][hh*2+0];
                float vy = acc[mi][ni][hh*2+1];
                size_t idx = ((size_t)(b*SEQ + s))*EMB + h*HD + d;
                __nv_bfloat162 h2 = hi2_of(vx, vy);
                *(__nv_bfloat162*)&g_xhi[idx] = h2;
                *(__nv_bfloat162*)&g_xlo[idx] = lo2_of(vx, vy, h2);
            }
        }
}

// ---------------------------------------------------------------------------
extern "C" void kernel_launch(void* const* d_in, const int* in_sizes, int n_in,
                              void* d_out, int out_size)
{
    const float* x  = (const float*)d_in[0];
    const float* bq = (const float*)d_in[5];
    const float* bk = (const float*)d_in[6];
    const float* bv = (const float*)d_in[7];
    const float* bo = (const float*)d_in[8];
    float* out = (float*)d_out;

    float* attnW = (out_size >= (OUT0_ELEMS + OUT1_ELEMS)) ? (out + OUT0_ELEMS)
                                                           : (float*)0;
    float* Sbuf = attnW;
    if (!Sbuf) {
        void* p = 0;
        cudaGetSymbolAddress(&p, g_s_fallback);
        Sbuf = (float*)p;
    }

    cudaFuncSetAttribute(gemm_hmma,
                         cudaFuncAttributeMaxDynamicSharedMemorySize, GSMEM);
    cudaFuncSetAttribute(qk_hmma,
                         cudaFuncAttributeMaxDynamicSharedMemorySize, QKSMEM);
    cudaFuncSetAttribute(pv_hmma,
                         cudaFuncAttributeMaxDynamicSharedMemorySize, PVSMEM);

    // Split weights (transposed) and x into bf16 hi/lo
    split_w<<<dim3(32, 32, 4), dim3(32, 32)>>>(
        (const float*)d_in[1], (const float*)d_in[2],
        (const float*)d_in[3], (const float*)d_in[4]);
    split_x<<<MROWS*EMB/(256*4), 256>>>(x);

    dim3 gg(EMB/128, MROWS/128);   // (8, 64)
    gemm_hmma<<<gg, 256, GSMEM>>>(bq, (float*)0, 0, 1);
    gemm_hmma<<<gg, 256, GSMEM>>>(bk, (float*)0, 1, 2);
    gemm_hmma<<<gg, 256, GSMEM>>>(bv, (float*)0, 2, 3);

    qk_hmma<<<dim3(SEQ/128, SEQ/128, BATCH*NH), 256, QKSMEM>>>(Sbuf);
    rowstat_combine<<<NROWS/256, 256>>>();
    pv_hmma<<<dim3(SEQ/128, BATCH*NH), 256, PVSMEM>>>(Sbuf);

    gemm_hmma<<<gg, 256, GSMEM>>>(bo, out, 3, 0);
}